// round 1
// baseline (speedup 1.0000x reference)
#include <cuda_runtime.h>
#include <cstdint>

// Elementwise: y = min(((x + 1) * 0.75)^2, 10) over 8192*8192 fp32.
// Pure HBM-bound streaming kernel; float4 vectorized, coalesced.

__global__ __launch_bounds__(256) void elemwise_kernel(
    const float4* __restrict__ x, float4* __restrict__ y, int n4)
{
    int i = blockIdx.x * blockDim.x + threadIdx.x;
    if (i < n4) {
        float4 v = x[i];
        float4 r;
        float t0 = (v.x + 1.0f) * 0.75f;
        float t1 = (v.y + 1.0f) * 0.75f;
        float t2 = (v.z + 1.0f) * 0.75f;
        float t3 = (v.w + 1.0f) * 0.75f;
        r.x = fminf(t0 * t0, 10.0f);
        r.y = fminf(t1 * t1, 10.0f);
        r.z = fminf(t2 * t2, 10.0f);
        r.w = fminf(t3 * t3, 10.0f);
        y[i] = r;
    }
}

extern "C" void kernel_launch(void* const* d_in, const int* in_sizes, int n_in,
                              void* d_out, int out_size)
{
    const float* x = (const float*)d_in[0];
    float* y = (float*)d_out;
    int n = in_sizes[0];          // 67108864, divisible by 4
    int n4 = n >> 2;              // 16777216 float4
    int threads = 256;
    int blocks = (n4 + threads - 1) / threads;
    elemwise_kernel<<<blocks, threads>>>(
        (const float4*)x, (float4*)y, n4);
}

// round 3
// speedup vs baseline: 1.0215x; 1.0215x over previous
#include <cuda_runtime.h>
#include <cstdint>

// Elementwise: y = min(((x + 1) * 0.75)^2, 10) over 8192*8192 fp32.
// HBM-bound streaming. float4 x4-unrolled per thread (MLP=4 front-batched
// independent LDG.128), streaming cache hints (__ldcs/__stcs) since there
// is zero reuse (512 MiB through a 126 MB L2).

#define UNROLL 4

__global__ __launch_bounds__(256) void elemwise_kernel(
    const float4* __restrict__ x, float4* __restrict__ y, int n4)
{
    // Each block owns UNROLL consecutive tiles of 256 float4.
    int base = blockIdx.x * (256 * UNROLL) + threadIdx.x;

    float4 v[UNROLL];
    // Front-batched independent loads: MLP_p1 = UNROLL.
#pragma unroll
    for (int k = 0; k < UNROLL; k++) {
        int i = base + k * 256;
        if (i < n4) v[k] = __ldcs(&x[i]);
    }

#pragma unroll
    for (int k = 0; k < UNROLL; k++) {
        int i = base + k * 256;
        if (i < n4) {
            float t0 = (v[k].x + 1.0f) * 0.75f;
            float t1 = (v[k].y + 1.0f) * 0.75f;
            float t2 = (v[k].z + 1.0f) * 0.75f;
            float t3 = (v[k].w + 1.0f) * 0.75f;
            float4 r;
            r.x = fminf(t0 * t0, 10.0f);
            r.y = fminf(t1 * t1, 10.0f);
            r.z = fminf(t2 * t2, 10.0f);
            r.w = fminf(t3 * t3, 10.0f);
            __stcs(&y[i], r);
        }
    }
}

extern "C" void kernel_launch(void* const* d_in, const int* in_sizes, int n_in,
                              void* d_out, int out_size)
{
    const float* x = (const float*)d_in[0];
    float* y = (float*)d_out;
    int n = in_sizes[0];           // 67108864, divisible by 4
    int n4 = n >> 2;               // 16777216 float4
    int threads = 256;
    int per_block = threads * UNROLL;
    int blocks = (n4 + per_block - 1) / per_block;   // 16384
    elemwise_kernel<<<blocks, threads>>>(
        (const float4*)x, (float4*)y, n4);
}

// round 4
// speedup vs baseline: 1.0218x; 1.0004x over previous
#include <cuda_runtime.h>
#include <cstdint>

// Elementwise: y = min(((x + 1) * 0.75)^2, 10) over 8192*8192 fp32.
// HBM-bound streaming. Exact-size fast path: no bounds predicates, 8
// independent front-batched LDG.128 per thread (MLP_p1=8), streaming
// cache hints (zero reuse: 512 MiB through 126 MB L2).

#define THREADS 256
#define UNROLL  8

__device__ __forceinline__ float4 f4map(float4 v)
{
    float t0 = (v.x + 1.0f) * 0.75f;
    float t1 = (v.y + 1.0f) * 0.75f;
    float t2 = (v.z + 1.0f) * 0.75f;
    float t3 = (v.w + 1.0f) * 0.75f;
    float4 r;
    r.x = fminf(t0 * t0, 10.0f);
    r.y = fminf(t1 * t1, 10.0f);
    r.z = fminf(t2 * t2, 10.0f);
    r.w = fminf(t3 * t3, 10.0f);
    return r;
}

// Fast path: grid*THREADS*UNROLL == n4 exactly. No predicates at all.
__global__ __launch_bounds__(THREADS) void elemwise_exact(
    const float4* __restrict__ x, float4* __restrict__ y)
{
    int base = blockIdx.x * (THREADS * UNROLL) + threadIdx.x;

    float4 v[UNROLL];
#pragma unroll
    for (int k = 0; k < UNROLL; k++)
        v[k] = __ldcs(&x[base + k * THREADS]);

#pragma unroll
    for (int k = 0; k < UNROLL; k++)
        __stcs(&y[base + k * THREADS], f4map(v[k]));
}

// Generic fallback (predicated) — only used if size doesn't divide.
__global__ __launch_bounds__(THREADS) void elemwise_pred(
    const float4* __restrict__ x, float4* __restrict__ y, int n4)
{
    int base = blockIdx.x * (THREADS * UNROLL) + threadIdx.x;
#pragma unroll
    for (int k = 0; k < UNROLL; k++) {
        int i = base + k * THREADS;
        if (i < n4) __stcs(&y[i], f4map(__ldcs(&x[i])));
    }
}

extern "C" void kernel_launch(void* const* d_in, const int* in_sizes, int n_in,
                              void* d_out, int out_size)
{
    const float4* x = (const float4*)d_in[0];
    float4* y = (float4*)d_out;
    int n = in_sizes[0];            // 67108864
    int n4 = n >> 2;                // 16777216 float4
    int per_block = THREADS * UNROLL;  // 2048

    if (n4 % per_block == 0) {
        int blocks = n4 / per_block;   // 8192
        elemwise_exact<<<blocks, THREADS>>>(x, y);
    } else {
        int blocks = (n4 + per_block - 1) / per_block;
        elemwise_pred<<<blocks, THREADS>>>(x, y, n4);
    }
}